// round 11
// baseline (speedup 1.0000x reference)
#include <cuda_runtime.h>
#include <cstdint>

#define DDIM 256
#define KC   512
#define BM   64
#define KN   64
#define NCH  (KC / KN)          // 8 code chunks
#define NMAX 131072
#define SLOTS 32
#define RSTRIDE 528             // 33x16B row stride: conflict-free ldmatrix (proven)
#define TILE_B  (BM * RSTRIDE)  // 33792
#define DYN_SMEM (3 * TILE_B)   // A + 2x B buffers = 101376

__device__ float g_esq[KC];
__device__ float g_zsq[NMAX];
__device__ int   g_emax_bits;                 // max_k ||e_k|| as float bits
__device__ uint32_t g_cbb[KC * DDIM / 2];     // bf16x2 codebook (256 KB)

__device__ __forceinline__ uint32_t sm_u32(const void* p) {
    uint32_t a;
    asm("{ .reg .u64 t; cvta.to.shared.u64 t, %1; cvt.u32.u64 %0, t; }"
        : "=r"(a) : "l"(p));
    return a;
}
#define STS128(a, r0, r1, r2, r3) \
    asm volatile("st.shared.v4.b32 [%0], {%1, %2, %3, %4};" \
                 :: "r"(a), "r"(r0), "r"(r1), "r"(r2), "r"(r3) : "memory")
#define LDMX4(r0, r1, r2, r3, addr) \
    asm volatile("ldmatrix.sync.aligned.m8n8.x4.shared.b16 {%0,%1,%2,%3}, [%4];" \
                 : "=r"(r0), "=r"(r1), "=r"(r2), "=r"(r3) : "r"(addr))
#define MMA16816(c, a0, a1, a2, a3, b0, b1) \
    asm volatile("mma.sync.aligned.m16n8k16.row.col.f32.bf16.bf16.f32 " \
                 "{%0,%1,%2,%3}, {%4,%5,%6,%7}, {%8,%9}, {%0,%1,%2,%3};" \
                 : "+f"((c)[0]), "+f"((c)[1]), "+f"((c)[2]), "+f"((c)[3]) \
                 : "r"(a0), "r"(a1), "r"(a2), "r"(a3), "r"(b0), "r"(b1))
#define CPASYNC16(dst, src) \
    asm volatile("cp.async.cg.shared.global [%0], [%1], 16;" \
                 :: "r"(dst), "l"(src) : "memory")
#define CPCOMMIT() asm volatile("cp.async.commit_group;" ::: "memory")
#define CPWAIT1()  asm volatile("cp.async.wait_group 1;" ::: "memory")
#define CPWAIT0()  asm volatile("cp.async.wait_group 0;" ::: "memory")

// ---- fused prologue: codebook bf16 convert + bitwise row sums (R3-proven) --
#define CVT_BLKS 512
__global__ __launch_bounds__(128)
void prep(const float* __restrict__ z, const float* __restrict__ cb, int nbz) {
    const int b = blockIdx.x;
    const int t = threadIdx.x;
    if (b < CVT_BLKS) {                         // bf16x2 codebook convert
        int i = b * 128 + t;                    // 65536 pairs
        float2 f = reinterpret_cast<const float2*>(cb)[i];
        uint32_t p;
        asm("cvt.rn.bf16x2.f32 %0, %1, %2;" : "=r"(p) : "f"(f.y), "f"(f.x));
        g_cbb[i] = p;
        return;
    }
    __shared__ float tile[128][33];
    const int rb = b - CVT_BLKS;
    const bool is_cb = (rb >= nbz);
    const float* src = is_cb ? cb : z;
    const int r0 = (is_cb ? (rb - nbz) : rb) * 128;
    float acc = 0.f;
    for (int d0 = 0; d0 < DDIM; d0 += 32) {
        __syncthreads();
        for (int e = t; e < 128 * 32; e += 128) {
            int r = e >> 5, c = e & 31;
            tile[r][c] = src[(size_t)(r0 + r) * DDIM + d0 + c];
        }
        __syncthreads();
        #pragma unroll
        for (int c = 0; c < 32; c++) {
            float v = tile[t][c];
            acc = __fadd_rn(acc, __fmul_rn(v, v));   // strict sequential order
        }
    }
    if (is_cb) {
        g_esq[r0 + t] = acc;
        atomicMax(&g_emax_bits, __float_as_int(sqrtf(acc)));
    } else {
        g_zsq[r0 + t] = acc;
    }
}

// --------------------------------- main ---------------------------------
__global__ __launch_bounds__(256)
void vq_main(const float* __restrict__ z, const float* __restrict__ cb,
             float* __restrict__ out, long long qoff4) {
    extern __shared__ __align__(16) char dsm[];
    __shared__ float s_esq[KC];                  // 2 KB: esq staged once
    __shared__ int   s_cnt[BM];
    __shared__ unsigned short s_candk[BM][SLOTS];
    __shared__ float s_rowmin2[BM][2];
    __shared__ int   s_ri[BM][4];
    __shared__ float s_rv[BM][4];
    __shared__ int   bidx[BM];

    const int tid = threadIdx.x;
    const int w   = tid >> 5;
    const int l   = tid & 31;
    const int m0  = blockIdx.x * BM;
    const uint32_t Ab  = sm_u32(dsm);
    const uint32_t Bb0 = Ab + TILE_B;
    const uint32_t Bb1 = Bb0 + TILE_B;

    if (tid < BM) s_cnt[tid] = 0;
    s_esq[tid]       = g_esq[tid];
    s_esq[tid + 256] = g_esq[tid + 256];

    auto prefetchB = [&](int kt, uint32_t Bb) {
        const char* src = reinterpret_cast<const char*>(g_cbb)
                        + (size_t)kt * KN * DDIM * 2;
        #pragma unroll
        for (int it = 0; it < 8; it++) {
            int u = tid + it * 256;            // 0..2047: 64 rows x 32 x 16B
            int r = u >> 5, c = u & 31;
            CPASYNC16(Bb + (uint32_t)(r * RSTRIDE + c * 16),
                      src + (size_t)r * 512 + c * 16);
        }
    };

    prefetchB(0, Bb0); CPCOMMIT();
    {   // load A tile: fp32 -> bf16 rn -> padded smem rows
        const float* src = z + (size_t)m0 * DDIM;
        #pragma unroll
        for (int it = 0; it < 8; it++) {
            int u = tid + it * 256;
            int r = u >> 5, c = u & 31;
            const float* p = src + (size_t)r * DDIM + c * 8;
            float4 f0 = __ldg(reinterpret_cast<const float4*>(p));
            float4 f1 = __ldg(reinterpret_cast<const float4*>(p + 4));
            uint32_t p0, p1, p2, p3;
            asm("cvt.rn.bf16x2.f32 %0, %1, %2;" : "=r"(p0) : "f"(f0.y), "f"(f0.x));
            asm("cvt.rn.bf16x2.f32 %0, %1, %2;" : "=r"(p1) : "f"(f0.w), "f"(f0.z));
            asm("cvt.rn.bf16x2.f32 %0, %1, %2;" : "=r"(p2) : "f"(f1.y), "f"(f1.x));
            asm("cvt.rn.bf16x2.f32 %0, %1, %2;" : "=r"(p3) : "f"(f1.w), "f"(f1.z));
            STS128(Ab + (uint32_t)(r * RSTRIDE + c * 16), p0, p1, p2, p3);
        }
    }
    prefetchB(1, Bb1); CPCOMMIT();
    CPWAIT1();                       // chunk-0 data landed (chunk-1 may fly)
    __syncthreads();

    const int wr = w & 3;              // row group: rows wr*16 .. +16
    const int wc = w >> 2;             // code half of each chunk
    const int mid = l >> 3, rr = l & 7;
    const int rA = wr * 16 + (l >> 2);
    const int rB = rA + 8;
    const float zsqA = g_zsq[m0 + rA];
    const float zsqB = g_zsq[m0 + rB];
    const float emax = __int_as_float(g_emax_bits);
    // two-sided containment: W2 >= 2*eps_d, eps_d = 4*2^-8*||z||*emax (+ slack)
    const float W2A = 8.0f * 0.00390625f * sqrtf(zsqA) * emax + 1.0e-3f;
    const float W2B = 8.0f * 0.00390625f * sqrtf(zsqB) * emax + 1.0e-3f;
    float rowMinA = 3.4e38f, rowMinB = 3.4e38f;

    for (int kt = 0; kt < NCH; kt++) {
        const uint32_t Bb = (kt & 1) ? Bb1 : Bb0;
        float acc[4][4];
        #pragma unroll
        for (int nt = 0; nt < 4; nt++)
            #pragma unroll
            for (int c = 0; c < 4; c++) acc[nt][c] = 0.f;

        const uint32_t Abase = Ab + (uint32_t)((wr * 16 + (mid & 1) * 8 + rr)
                              * RSTRIDE + (mid >> 1) * 16);
        const uint32_t Bbase = Bb + (uint32_t)((wc * 32 + (mid >> 1) * 8 + rr)
                              * RSTRIDE + (mid & 1) * 16);
        #pragma unroll
        for (int ks = 0; ks < 16; ks++) {
            uint32_t a0, a1, a2, a3;
            LDMX4(a0, a1, a2, a3, Abase + ks * 32);
            #pragma unroll
            for (int ntp = 0; ntp < 2; ntp++) {
                uint32_t b0, b1, b2, b3;
                LDMX4(b0, b1, b2, b3,
                      Bbase + (uint32_t)(ntp * 16 * RSTRIDE) + ks * 32);
                MMA16816(acc[2 * ntp],     a0, a1, a2, a3, b0, b1);
                MMA16816(acc[2 * ntp + 1], a0, a1, a2, a3, b2, b3);
            }
        }

        // pass 1: running per-row min (this warp's code half)
        float tminA = 3.4e38f, tminB = 3.4e38f;
        #pragma unroll
        for (int nt = 0; nt < 4; nt++) {
            #pragma unroll
            for (int c = 0; c < 2; c++) {
                int col = kt * KN + wc * 32 + nt * 8 + 2 * (l & 3) + c;
                float esq = s_esq[col];
                float va = __fadd_rn(fmaf(-2.f, acc[nt][c],     zsqA), esq);
                float vb = __fadd_rn(fmaf(-2.f, acc[nt][2 + c], zsqB), esq);
                tminA = fminf(tminA, va);
                tminB = fminf(tminB, vb);
            }
        }
        tminA = fminf(tminA, __shfl_xor_sync(0xffffffffu, tminA, 1));
        tminA = fminf(tminA, __shfl_xor_sync(0xffffffffu, tminA, 2));
        tminB = fminf(tminB, __shfl_xor_sync(0xffffffffu, tminB, 1));
        tminB = fminf(tminB, __shfl_xor_sync(0xffffffffu, tminB, 2));
        rowMinA = fminf(rowMinA, tminA);
        rowMinB = fminf(rowMinB, tminB);
        const float thrA = rowMinA + W2A;   // running thr >= final thr
        const float thrB = rowMinB + W2B;

        // pass 2: collect candidate indices within the running window
        #pragma unroll
        for (int nt = 0; nt < 4; nt++) {
            #pragma unroll
            for (int c = 0; c < 2; c++) {
                int col = kt * KN + wc * 32 + nt * 8 + 2 * (l & 3) + c;
                float esq = s_esq[col];
                float va = __fadd_rn(fmaf(-2.f, acc[nt][c],     zsqA), esq);
                float vb = __fadd_rn(fmaf(-2.f, acc[nt][2 + c], zsqB), esq);
                if (va <= thrA) {
                    int s = atomicAdd(&s_cnt[rA], 1);
                    if (s < SLOTS) s_candk[rA][s] = (unsigned short)col;
                }
                if (vb <= thrB) {
                    int s = atomicAdd(&s_cnt[rB], 1);
                    if (s < SLOTS) s_candk[rB][s] = (unsigned short)col;
                }
            }
        }

        __syncthreads();                 // all warps done reading buf kt
        if (kt + 2 < NCH) { prefetchB(kt + 2, Bb); CPCOMMIT(); }
        if (kt + 1 < NCH) {
            if (kt + 2 < NCH) CPWAIT1(); else CPWAIT0();
            __syncthreads();             // buf kt+1 visible to all warps
        }
    }

    if ((l & 3) == 0) {
        s_rowmin2[rA][wc] = rowMinA;
        s_rowmin2[rB][wc] = rowMinB;
    }
    __syncthreads();

    // ---- exact recheck: strictly-sequential FMA (bitwise reference pipeline)
    // 4 threads per row, candidate slots strided.
    {
        const int row = tid & 63;
        const int sl  = tid >> 6;
        const int cntr = s_cnt[row];
        const float zsq = g_zsq[m0 + row];
        const float* zr = z + (size_t)(m0 + row) * DDIM;
        float bv = 3.4e38f;
        int   bi = 0x7fffffff;
        if (cntr <= SLOTS) {
            for (int s = sl; s < cntr; s += 4) {
                int k = s_candk[row][s];
                const float* cr = cb + (size_t)k * DDIM;
                float acc = 0.f;
                for (int d = 0; d < DDIM; d++)
                    acc = fmaf(__ldg(zr + d), __ldg(cr + d), acc);
                float v = __fadd_rn(fmaf(-2.f, acc, zsq), s_esq[k]);
                if (v < bv || (v == bv && k < bi)) { bv = v; bi = k; }
            }
        } else {   // overflow fallback (P ~ 0 with SLOTS=32): parallel full scan
            for (int k = sl; k < KC; k += 4) {
                const float* cr = cb + (size_t)k * DDIM;
                float acc = 0.f;
                for (int d = 0; d < DDIM; d++)
                    acc = fmaf(__ldg(zr + d), __ldg(cr + d), acc);
                float v = __fadd_rn(fmaf(-2.f, acc, zsq), s_esq[k]);
                if (v < bv || (v == bv && k < bi)) { bv = v; bi = k; }
            }
        }
        s_rv[row][sl] = bv;
        s_ri[row][sl] = bi;
    }
    __syncthreads();
    if (tid < BM) {
        float bv = s_rv[tid][0];
        int   bi = s_ri[tid][0];
        #pragma unroll
        for (int s = 1; s < 4; s++) {
            float v = s_rv[tid][s];
            int   k = s_ri[tid][s];
            if (v < bv || (v == bv && k < bi)) { bv = v; bi = k; }
        }
        bidx[tid] = bi;
    }
    __syncthreads();

    // ---- gather + write: out[0:ND] = fl(z + fl(zq - z)) (STE), out[ND:] = zq
    const float4* cb4 = reinterpret_cast<const float4*>(cb);
    const float4* z4  = reinterpret_cast<const float4*>(z);
    float4* out4 = reinterpret_cast<float4*>(out);
    const long long base = (long long)m0 * (DDIM / 4);
    for (int e = tid; e < BM * (DDIM / 4); e += 256) {
        int r = e >> 6;
        int c = e & 63;
        int k = bidx[r];
        float4 q  = cb4[k * (DDIM / 4) + c];
        float4 ze = z4[base + (long long)r * (DDIM / 4) + c];
        float4 st;
        st.x = __fadd_rn(ze.x, __fsub_rn(q.x, ze.x));
        st.y = __fadd_rn(ze.y, __fsub_rn(q.y, ze.y));
        st.z = __fadd_rn(ze.z, __fsub_rn(q.z, ze.z));
        st.w = __fadd_rn(ze.w, __fsub_rn(q.w, ze.w));
        out4[base + (long long)r * (DDIM / 4) + c] = st;
        if (qoff4 > 0)
            out4[qoff4 + base + (long long)r * (DDIM / 4) + c] = q;
    }
}

extern "C" void kernel_launch(void* const* d_in, const int* in_sizes, int n_in,
                              void* d_out, int out_size) {
    const float* z  = (const float*)d_in[0];
    const float* cb = (const float*)d_in[1];
    int Nrows = in_sizes[0] / DDIM;
    long long ND = (long long)Nrows * DDIM;
    long long qoff4 = ((long long)out_size >= 2 * ND) ? (ND / 4) : 0;

    cudaFuncSetAttribute(vq_main, cudaFuncAttributeMaxDynamicSharedMemorySize,
                         DYN_SMEM);
    cudaFuncSetAttribute(vq_main,
                         cudaFuncAttributePreferredSharedMemoryCarveout, 100);

    int nbz = Nrows / 128;
    prep<<<CVT_BLKS + nbz + KC / 128, 128>>>(z, cb, nbz);
    vq_main<<<Nrows / BM, 256, DYN_SMEM>>>(z, cb, (float*)d_out, qoff4);
}

// round 13
// speedup vs baseline: 1.6570x; 1.6570x over previous
#include <cuda_runtime.h>
#include <cstdint>

#define DDIM 256
#define KC   512
#define BM   64
#define KN   64
#define NCH  (KC / KN)          // 8 code chunks
#define NMAX 131072
#define SLOTS 32
#define RSTRIDE 528             // 33x16B row stride: conflict-free ldmatrix (proven)
#define TILE_B  (BM * RSTRIDE)  // 33792
#define DYN_SMEM (2 * TILE_B)   // A + single B buffer = 67584

__device__ float g_esq[KC];
__device__ float g_zsq[NMAX];
__device__ int   g_emax_bits;                 // max_k ||e_k|| as float bits
__device__ uint32_t g_cbb[KC * DDIM / 2];     // bf16x2 codebook (256 KB)

__device__ __forceinline__ uint32_t sm_u32(const void* p) {
    uint32_t a;
    asm("{ .reg .u64 t; cvta.to.shared.u64 t, %1; cvt.u32.u64 %0, t; }"
        : "=r"(a) : "l"(p));
    return a;
}
#define STS128(a, r0, r1, r2, r3) \
    asm volatile("st.shared.v4.b32 [%0], {%1, %2, %3, %4};" \
                 :: "r"(a), "r"(r0), "r"(r1), "r"(r2), "r"(r3) : "memory")
#define LDMX4(r0, r1, r2, r3, addr) \
    asm volatile("ldmatrix.sync.aligned.m8n8.x4.shared.b16 {%0,%1,%2,%3}, [%4];" \
                 : "=r"(r0), "=r"(r1), "=r"(r2), "=r"(r3) : "r"(addr))
#define MMA16816(c, a0, a1, a2, a3, b0, b1) \
    asm volatile("mma.sync.aligned.m16n8k16.row.col.f32.bf16.bf16.f32 " \
                 "{%0,%1,%2,%3}, {%4,%5,%6,%7}, {%8,%9}, {%0,%1,%2,%3};" \
                 : "+f"((c)[0]), "+f"((c)[1]), "+f"((c)[2]), "+f"((c)[3]) \
                 : "r"(a0), "r"(a1), "r"(a2), "r"(a3), "r"(b0), "r"(b1))
#define CPASYNC16(dst, src) \
    asm volatile("cp.async.cg.shared.global [%0], [%1], 16;" \
                 :: "r"(dst), "l"(src) : "memory")
#define CPCOMMIT() asm volatile("cp.async.commit_group;" ::: "memory")
#define CPWAIT0()  asm volatile("cp.async.wait_group 0;" ::: "memory")

// -------- prologue A: codebook fp32 -> bf16 (rn), packed pairs --------
__global__ void cvt_cb(const float* __restrict__ cb) {
    int i = blockIdx.x * blockDim.x + threadIdx.x;
    if (i < KC * DDIM / 2) {
        float2 f = reinterpret_cast<const float2*>(cb)[i];
        uint32_t p;
        asm("cvt.rn.bf16x2.f32 %0, %1, %2;" : "=r"(p) : "f"(f.y), "f"(f.x));
        g_cbb[i] = p;
    }
}

// -------- prologue B: bitwise-exact sum(x*x) rows (R3-proven order) --------
__global__ __launch_bounds__(128)
void rowsq_all(const float* __restrict__ z, const float* __restrict__ cb,
               int nbz) {
    __shared__ float tile[128][33];
    const int b = blockIdx.x;
    const bool is_cb = (b >= nbz);
    const float* src = is_cb ? cb : z;
    const int r0 = (is_cb ? (b - nbz) : b) * 128;
    const int t = threadIdx.x;
    float acc = 0.f;
    for (int d0 = 0; d0 < DDIM; d0 += 32) {
        __syncthreads();
        for (int e = t; e < 128 * 32; e += 128) {
            int r = e >> 5, c = e & 31;
            tile[r][c] = src[(size_t)(r0 + r) * DDIM + d0 + c];
        }
        __syncthreads();
        #pragma unroll
        for (int c = 0; c < 32; c++) {
            float v = tile[t][c];
            acc = __fadd_rn(acc, __fmul_rn(v, v));
        }
    }
    if (is_cb) {
        g_esq[r0 + t] = acc;
        atomicMax(&g_emax_bits, __float_as_int(sqrtf(acc)));
    } else {
        g_zsq[r0 + t] = acc;
    }
}

// --------------------------------- main ---------------------------------
__global__ __launch_bounds__(256, 2)
void vq_main(const float* __restrict__ z, const float* __restrict__ cb,
             float* __restrict__ out, long long qoff4) {
    extern __shared__ __align__(16) char dsm[];
    __shared__ int   s_cnt[BM];
    __shared__ int   s_candk[BM][SLOTS];
    __shared__ float s_candv[BM][SLOTS];
    __shared__ float s_rowmin2[BM][2];      // per code-half running min
    __shared__ int   s_ri[BM][4];
    __shared__ float s_rv[BM][4];
    __shared__ int   bidx[BM];

    const int tid = threadIdx.x;
    const int w   = tid >> 5;
    const int l   = tid & 31;
    const int m0  = blockIdx.x * BM;
    const uint32_t Ab = sm_u32(dsm);
    const uint32_t Bb = Ab + TILE_B;

    if (tid < BM) s_cnt[tid] = 0;

    auto prefetchB = [&](int kt) {
        const char* src = reinterpret_cast<const char*>(g_cbb)
                        + (size_t)kt * KN * DDIM * 2;
        #pragma unroll
        for (int it = 0; it < 8; it++) {
            int u = tid + it * 256;            // 0..2047: 64 rows x 32 x 16B
            int r = u >> 5, c = u & 31;
            CPASYNC16(Bb + (uint32_t)(r * RSTRIDE + c * 16),
                      src + (size_t)r * 512 + c * 16);
        }
    };

    prefetchB(0); CPCOMMIT();
    {   // load A tile: fp32 -> bf16 rn -> padded smem rows
        const float* src = z + (size_t)m0 * DDIM;
        #pragma unroll
        for (int it = 0; it < 8; it++) {
            int u = tid + it * 256;
            int r = u >> 5, c = u & 31;
            const float* p = src + (size_t)r * DDIM + c * 8;
            float4 f0 = __ldg(reinterpret_cast<const float4*>(p));
            float4 f1 = __ldg(reinterpret_cast<const float4*>(p + 4));
            uint32_t p0, p1, p2, p3;
            asm("cvt.rn.bf16x2.f32 %0, %1, %2;" : "=r"(p0) : "f"(f0.y), "f"(f0.x));
            asm("cvt.rn.bf16x2.f32 %0, %1, %2;" : "=r"(p1) : "f"(f0.w), "f"(f0.z));
            asm("cvt.rn.bf16x2.f32 %0, %1, %2;" : "=r"(p2) : "f"(f1.y), "f"(f1.x));
            asm("cvt.rn.bf16x2.f32 %0, %1, %2;" : "=r"(p3) : "f"(f1.w), "f"(f1.z));
            STS128(Ab + (uint32_t)(r * RSTRIDE + c * 16), p0, p1, p2, p3);
        }
    }
    CPWAIT0();
    __syncthreads();

    const int wr = w & 3;              // row group: rows wr*16 .. +16
    const int wc = w >> 2;             // code half of each chunk
    const int mid = l >> 3, rr = l & 7;
    const int rA = wr * 16 + (l >> 2);
    const int rB = rA + 8;
    const float zsqA = g_zsq[m0 + rA];
    const float zsqB = g_zsq[m0 + rB];
    const float emax = __int_as_float(g_emax_bits);
    // two-sided containment: W2 >= 2*eps_d, eps_d = 4*2^-8*||z||*emax (+ slack)
    const float W2A = 8.0f * 0.00390625f * sqrtf(zsqA) * emax + 1.0e-3f;
    const float W2B = 8.0f * 0.00390625f * sqrtf(zsqB) * emax + 1.0e-3f;
    float rowMinA = 3.4e38f, rowMinB = 3.4e38f;

    #pragma unroll 1
    for (int kt = 0; kt < NCH; kt++) {
        float acc[4][4];
        #pragma unroll
        for (int nt = 0; nt < 4; nt++)
            #pragma unroll
            for (int c = 0; c < 4; c++) acc[nt][c] = 0.f;

        #pragma unroll
        for (int ks = 0; ks < 16; ks++) {
            uint32_t a0, a1, a2, a3;
            LDMX4(a0, a1, a2, a3,
                  Ab + (uint32_t)((wr * 16 + (mid & 1) * 8 + rr) * RSTRIDE
                       + (ks * 2 + (mid >> 1)) * 16));
            #pragma unroll
            for (int ntp = 0; ntp < 2; ntp++) {
                uint32_t b0, b1, b2, b3;
                LDMX4(b0, b1, b2, b3,
                      Bb + (uint32_t)((wc * 32 + ntp * 16 + (mid >> 1) * 8 + rr)
                           * RSTRIDE + (ks * 2 + (mid & 1)) * 16));
                MMA16816(acc[2 * ntp],     a0, a1, a2, a3, b0, b1);
                MMA16816(acc[2 * ntp + 1], a0, a1, a2, a3, b2, b3);
            }
        }

        // pass 1: running per-row min (this warp's code half)
        float tminA = 3.4e38f, tminB = 3.4e38f;
        #pragma unroll
        for (int nt = 0; nt < 4; nt++) {
            #pragma unroll
            for (int c = 0; c < 2; c++) {
                int col = kt * KN + wc * 32 + nt * 8 + 2 * (l & 3) + c;
                float esq = __ldg(&g_esq[col]);
                float va = __fadd_rn(fmaf(-2.f, acc[nt][c],     zsqA), esq);
                float vb = __fadd_rn(fmaf(-2.f, acc[nt][2 + c], zsqB), esq);
                tminA = fminf(tminA, va);
                tminB = fminf(tminB, vb);
            }
        }
        tminA = fminf(tminA, __shfl_xor_sync(0xffffffffu, tminA, 1));
        tminA = fminf(tminA, __shfl_xor_sync(0xffffffffu, tminA, 2));
        tminB = fminf(tminB, __shfl_xor_sync(0xffffffffu, tminB, 1));
        tminB = fminf(tminB, __shfl_xor_sync(0xffffffffu, tminB, 2));
        rowMinA = fminf(rowMinA, tminA);
        rowMinB = fminf(rowMinB, tminB);
        const float thrA = rowMinA + W2A;   // running thr >= final thr:
        const float thrB = rowMinB + W2B;   // containment preserved

        // pass 2: collect (k, v) candidates within the running window
        #pragma unroll
        for (int nt = 0; nt < 4; nt++) {
            #pragma unroll
            for (int c = 0; c < 2; c++) {
                int col = kt * KN + wc * 32 + nt * 8 + 2 * (l & 3) + c;
                float esq = __ldg(&g_esq[col]);
                float va = __fadd_rn(fmaf(-2.f, acc[nt][c],     zsqA), esq);
                float vb = __fadd_rn(fmaf(-2.f, acc[nt][2 + c], zsqB), esq);
                if (va <= thrA) {
                    int s = atomicAdd(&s_cnt[rA], 1);
                    if (s < SLOTS) { s_candk[rA][s] = col; s_candv[rA][s] = va; }
                }
                if (vb <= thrB) {
                    int s = atomicAdd(&s_cnt[rB], 1);
                    if (s < SLOTS) { s_candk[rB][s] = col; s_candv[rB][s] = vb; }
                }
            }
        }

        __syncthreads();                     // all warps done reading B tile
        if (kt + 1 < NCH) {
            prefetchB(kt + 1); CPCOMMIT(); CPWAIT0();
            __syncthreads();
        }
    }

    if ((l & 3) == 0) {
        s_rowmin2[rA][wc] = rowMinA;
        s_rowmin2[rB][wc] = rowMinB;
    }
    __syncthreads();

    // ---- refilter by FINAL threshold, then exact sequential-FMA recheck ----
    {
        const int row = tid & 63;
        const int sl  = tid >> 6;
        const int cntr = s_cnt[row];
        const float zsq = g_zsq[m0 + row];
        const float w2  = 8.0f * 0.00390625f * sqrtf(zsq) * emax + 1.0e-3f;
        const float thr = fminf(s_rowmin2[row][0], s_rowmin2[row][1]) + w2;
        const float* zr = z + (size_t)(m0 + row) * DDIM;
        float bv = 3.4e38f;
        int   bi = 0x7fffffff;
        if (cntr <= SLOTS) {
            for (int s = sl; s < cntr; s += 4) {
                if (s_candv[row][s] > thr) continue;   // final-window refilter
                int k = s_candk[row][s];
                const float* cr = cb + (size_t)k * DDIM;
                float acc = 0.f;
                for (int d = 0; d < DDIM; d++)
                    acc = fmaf(__ldg(zr + d), __ldg(cr + d), acc);
                float v = __fadd_rn(fmaf(-2.f, acc, zsq), __ldg(&g_esq[k]));
                if (v < bv || (v == bv && k < bi)) { bv = v; bi = k; }
            }
        } else {   // overflow fallback (P ~ 0 with SLOTS=32): parallel full scan
            for (int k = sl; k < KC; k += 4) {
                const float* cr = cb + (size_t)k * DDIM;
                float acc = 0.f;
                for (int d = 0; d < DDIM; d++)
                    acc = fmaf(__ldg(zr + d), __ldg(cr + d), acc);
                float v = __fadd_rn(fmaf(-2.f, acc, zsq), __ldg(&g_esq[k]));
                if (v < bv || (v == bv && k < bi)) { bv = v; bi = k; }
            }
        }
        s_rv[row][sl] = bv;
        s_ri[row][sl] = bi;
    }
    __syncthreads();
    if (tid < BM) {
        float bv = s_rv[tid][0];
        int   bi = s_ri[tid][0];
        #pragma unroll
        for (int s = 1; s < 4; s++) {
            float v = s_rv[tid][s];
            int   k = s_ri[tid][s];
            if (v < bv || (v == bv && k < bi)) { bv = v; bi = k; }
        }
        bidx[tid] = bi;
    }
    __syncthreads();

    // ---- gather + write: out[0:ND] = fl(z + fl(zq - z)) (STE), out[ND:] = zq
    const float4* cb4 = reinterpret_cast<const float4*>(cb);
    const float4* z4  = reinterpret_cast<const float4*>(z);
    float4* out4 = reinterpret_cast<float4*>(out);
    const long long base = (long long)m0 * (DDIM / 4);
    for (int e = tid; e < BM * (DDIM / 4); e += 256) {
        int r = e >> 6;
        int c = e & 63;
        int k = bidx[r];
        float4 q  = cb4[k * (DDIM / 4) + c];
        float4 ze = z4[base + (long long)r * (DDIM / 4) + c];
        float4 st;
        st.x = __fadd_rn(ze.x, __fsub_rn(q.x, ze.x));
        st.y = __fadd_rn(ze.y, __fsub_rn(q.y, ze.y));
        st.z = __fadd_rn(ze.z, __fsub_rn(q.z, ze.z));
        st.w = __fadd_rn(ze.w, __fsub_rn(q.w, ze.w));
        out4[base + (long long)r * (DDIM / 4) + c] = st;
        if (qoff4 > 0)
            out4[qoff4 + base + (long long)r * (DDIM / 4) + c] = q;
    }
}

extern "C" void kernel_launch(void* const* d_in, const int* in_sizes, int n_in,
                              void* d_out, int out_size) {
    const float* z  = (const float*)d_in[0];
    const float* cb = (const float*)d_in[1];
    int Nrows = in_sizes[0] / DDIM;
    long long ND = (long long)Nrows * DDIM;
    long long qoff4 = ((long long)out_size >= 2 * ND) ? (ND / 4) : 0;

    cudaFuncSetAttribute(vq_main, cudaFuncAttributeMaxDynamicSharedMemorySize,
                         DYN_SMEM);

    int nbz = Nrows / 128;
    cvt_cb<<<(KC * DDIM / 2 + 255) / 256, 256>>>(cb);
    rowsq_all<<<nbz + KC / 128, 128>>>(z, cb, nbz);
    vq_main<<<Nrows / BM, 256, DYN_SMEM>>>(z, cb, (float*)d_out, qoff4);
}

// round 14
// speedup vs baseline: 4.2133x; 2.5427x over previous
#include <cuda_runtime.h>
#include <cstdint>

#define DDIM 256
#define KC   512
#define BM   64
#define KN   64
#define NCH  (KC / KN)          // 8 code chunks
#define NMAX 131072
#define SLOTS 32
#define RSTRIDE 528             // 33x16B row stride: conflict-free ldmatrix (proven)
#define TILE_B  (BM * RSTRIDE)  // 33792
#define DYN_SMEM (2 * TILE_B)   // A + single B buffer = 67584

__device__ float g_esq[KC];
__device__ float g_zsq[NMAX];
__device__ int   g_emax_bits;                 // max_k ||e_k|| as float bits
__device__ uint32_t g_cbb[KC * DDIM / 2];     // bf16x2 codebook (256 KB)

__device__ __forceinline__ uint32_t sm_u32(const void* p) {
    uint32_t a;
    asm("{ .reg .u64 t; cvta.to.shared.u64 t, %1; cvt.u32.u64 %0, t; }"
        : "=r"(a) : "l"(p));
    return a;
}
#define STS128(a, r0, r1, r2, r3) \
    asm volatile("st.shared.v4.b32 [%0], {%1, %2, %3, %4};" \
                 :: "r"(a), "r"(r0), "r"(r1), "r"(r2), "r"(r3) : "memory")
#define LDMX4(r0, r1, r2, r3, addr) \
    asm volatile("ldmatrix.sync.aligned.m8n8.x4.shared.b16 {%0,%1,%2,%3}, [%4];" \
                 : "=r"(r0), "=r"(r1), "=r"(r2), "=r"(r3) : "r"(addr))
#define MMA16816(c, a0, a1, a2, a3, b0, b1) \
    asm volatile("mma.sync.aligned.m16n8k16.row.col.f32.bf16.bf16.f32 " \
                 "{%0,%1,%2,%3}, {%4,%5,%6,%7}, {%8,%9}, {%0,%1,%2,%3};" \
                 : "+f"((c)[0]), "+f"((c)[1]), "+f"((c)[2]), "+f"((c)[3]) \
                 : "r"(a0), "r"(a1), "r"(a2), "r"(a3), "r"(b0), "r"(b1))
#define CPASYNC16(dst, src) \
    asm volatile("cp.async.cg.shared.global [%0], [%1], 16;" \
                 :: "r"(dst), "l"(src) : "memory")
#define CPCOMMIT() asm volatile("cp.async.commit_group;" ::: "memory")
#define CPWAIT0()  asm volatile("cp.async.wait_group 0;" ::: "memory")

// ---- fused prologue: codebook bf16 convert + bitwise row sums (R3-proven) --
// One kernel => the timed graph has exactly 2 launches per replay, so ncu's
// "-s 5 -c 1" lands on vq_main (observability parity with R7/R11).
#define CVT_BLKS 512
__global__ __launch_bounds__(128)
void prep(const float* __restrict__ z, const float* __restrict__ cb, int nbz) {
    const int b = blockIdx.x;
    const int t = threadIdx.x;
    if (b < CVT_BLKS) {                         // bf16x2 codebook convert
        int i = b * 128 + t;                    // 65536 pairs
        float2 f = reinterpret_cast<const float2*>(cb)[i];
        uint32_t p;
        asm("cvt.rn.bf16x2.f32 %0, %1, %2;" : "=r"(p) : "f"(f.y), "f"(f.x));
        g_cbb[i] = p;
        return;
    }
    __shared__ float tile[128][33];
    const int rb = b - CVT_BLKS;
    const bool is_cb = (rb >= nbz);
    const float* src = is_cb ? cb : z;
    const int r0 = (is_cb ? (rb - nbz) : rb) * 128;
    float acc = 0.f;
    for (int d0 = 0; d0 < DDIM; d0 += 32) {
        __syncthreads();
        for (int e = t; e < 128 * 32; e += 128) {
            int r = e >> 5, c = e & 31;
            tile[r][c] = src[(size_t)(r0 + r) * DDIM + d0 + c];
        }
        __syncthreads();
        #pragma unroll
        for (int c = 0; c < 32; c++) {
            float v = tile[t][c];
            acc = __fadd_rn(acc, __fmul_rn(v, v));   // strict sequential order
        }
    }
    if (is_cb) {
        g_esq[r0 + t] = acc;
        atomicMax(&g_emax_bits, __float_as_int(sqrtf(acc)));
    } else {
        g_zsq[r0 + t] = acc;
    }
}

// ------------- main kernel: byte-for-byte the proven 766us R10 body ---------
__global__ __launch_bounds__(256)
void vq_main(const float* __restrict__ z, const float* __restrict__ cb,
             float* __restrict__ out, long long qoff4) {
    extern __shared__ __align__(16) char dsm[];
    __shared__ int   s_cnt[BM];
    __shared__ int   s_candk[BM][SLOTS];
    __shared__ float s_candv[BM][SLOTS];
    __shared__ float s_rowmin2[BM][2];      // per code-half running min
    __shared__ int   s_ri[BM][4];
    __shared__ float s_rv[BM][4];
    __shared__ int   bidx[BM];

    const int tid = threadIdx.x;
    const int w   = tid >> 5;
    const int l   = tid & 31;
    const int m0  = blockIdx.x * BM;
    const uint32_t Ab = sm_u32(dsm);
    const uint32_t Bb = Ab + TILE_B;

    if (tid < BM) s_cnt[tid] = 0;

    auto prefetchB = [&](int kt) {
        const char* src = reinterpret_cast<const char*>(g_cbb)
                        + (size_t)kt * KN * DDIM * 2;
        #pragma unroll
        for (int it = 0; it < 8; it++) {
            int u = tid + it * 256;            // 0..2047: 64 rows x 32 x 16B
            int r = u >> 5, c = u & 31;
            CPASYNC16(Bb + (uint32_t)(r * RSTRIDE + c * 16),
                      src + (size_t)r * 512 + c * 16);
        }
    };

    prefetchB(0); CPCOMMIT();
    {   // load A tile: fp32 -> bf16 rn -> padded smem rows
        const float* src = z + (size_t)m0 * DDIM;
        #pragma unroll
        for (int it = 0; it < 8; it++) {
            int u = tid + it * 256;
            int r = u >> 5, c = u & 31;
            const float* p = src + (size_t)r * DDIM + c * 8;
            float4 f0 = __ldg(reinterpret_cast<const float4*>(p));
            float4 f1 = __ldg(reinterpret_cast<const float4*>(p + 4));
            uint32_t p0, p1, p2, p3;
            asm("cvt.rn.bf16x2.f32 %0, %1, %2;" : "=r"(p0) : "f"(f0.y), "f"(f0.x));
            asm("cvt.rn.bf16x2.f32 %0, %1, %2;" : "=r"(p1) : "f"(f0.w), "f"(f0.z));
            asm("cvt.rn.bf16x2.f32 %0, %1, %2;" : "=r"(p2) : "f"(f1.y), "f"(f1.x));
            asm("cvt.rn.bf16x2.f32 %0, %1, %2;" : "=r"(p3) : "f"(f1.w), "f"(f1.z));
            STS128(Ab + (uint32_t)(r * RSTRIDE + c * 16), p0, p1, p2, p3);
        }
    }
    CPWAIT0();
    __syncthreads();

    const int wr = w & 3;              // row group: rows wr*16 .. +16
    const int wc = w >> 2;             // code half of each chunk
    const int mid = l >> 3, rr = l & 7;
    const int rA = wr * 16 + (l >> 2);
    const int rB = rA + 8;
    const float zsqA = g_zsq[m0 + rA];
    const float zsqB = g_zsq[m0 + rB];
    const float emax = __int_as_float(g_emax_bits);
    const float W2A = 4.0f * 0.00390625f * sqrtf(zsqA) * emax + 1.0e-3f;
    const float W2B = 4.0f * 0.00390625f * sqrtf(zsqB) * emax + 1.0e-3f;
    float rowMinA = 3.4e38f, rowMinB = 3.4e38f;

    for (int kt = 0; kt < NCH; kt++) {
        float acc[4][4];
        #pragma unroll
        for (int nt = 0; nt < 4; nt++)
            #pragma unroll
            for (int c = 0; c < 4; c++) acc[nt][c] = 0.f;

        #pragma unroll
        for (int ks = 0; ks < 16; ks++) {
            uint32_t a0, a1, a2, a3;
            LDMX4(a0, a1, a2, a3,
                  Ab + (uint32_t)((wr * 16 + (mid & 1) * 8 + rr) * RSTRIDE
                       + (ks * 2 + (mid >> 1)) * 16));
            #pragma unroll
            for (int ntp = 0; ntp < 2; ntp++) {
                uint32_t b0, b1, b2, b3;
                LDMX4(b0, b1, b2, b3,
                      Bb + (uint32_t)((wc * 32 + ntp * 16 + (mid >> 1) * 8 + rr)
                           * RSTRIDE + (ks * 2 + (mid & 1)) * 16));
                MMA16816(acc[2 * ntp],     a0, a1, a2, a3, b0, b1);
                MMA16816(acc[2 * ntp + 1], a0, a1, a2, a3, b2, b3);
            }
        }

        // pass 1: running per-row min (this warp's code half)
        float tminA = 3.4e38f, tminB = 3.4e38f;
        #pragma unroll
        for (int nt = 0; nt < 4; nt++) {
            #pragma unroll
            for (int c = 0; c < 2; c++) {
                int col = kt * KN + wc * 32 + nt * 8 + 2 * (l & 3) + c;
                float esq = __ldg(&g_esq[col]);
                float va = __fadd_rn(fmaf(-2.f, acc[nt][c],     zsqA), esq);
                float vb = __fadd_rn(fmaf(-2.f, acc[nt][2 + c], zsqB), esq);
                tminA = fminf(tminA, va);
                tminB = fminf(tminB, vb);
            }
        }
        tminA = fminf(tminA, __shfl_xor_sync(0xffffffffu, tminA, 1));
        tminA = fminf(tminA, __shfl_xor_sync(0xffffffffu, tminA, 2));
        tminB = fminf(tminB, __shfl_xor_sync(0xffffffffu, tminB, 1));
        tminB = fminf(tminB, __shfl_xor_sync(0xffffffffu, tminB, 2));
        rowMinA = fminf(rowMinA, tminA);
        rowMinB = fminf(rowMinB, tminB);
        const float thrA = rowMinA + W2A;   // running thr >= final thr:
        const float thrB = rowMinB + W2B;   // containment preserved

        // pass 2: collect (k, v) candidates within the running window
        #pragma unroll
        for (int nt = 0; nt < 4; nt++) {
            #pragma unroll
            for (int c = 0; c < 2; c++) {
                int col = kt * KN + wc * 32 + nt * 8 + 2 * (l & 3) + c;
                float esq = __ldg(&g_esq[col]);
                float va = __fadd_rn(fmaf(-2.f, acc[nt][c],     zsqA), esq);
                float vb = __fadd_rn(fmaf(-2.f, acc[nt][2 + c], zsqB), esq);
                if (va <= thrA) {
                    int s = atomicAdd(&s_cnt[rA], 1);
                    if (s < SLOTS) { s_candk[rA][s] = col; s_candv[rA][s] = va; }
                }
                if (vb <= thrB) {
                    int s = atomicAdd(&s_cnt[rB], 1);
                    if (s < SLOTS) { s_candk[rB][s] = col; s_candv[rB][s] = vb; }
                }
            }
        }

        __syncthreads();                     // all warps done reading B tile
        if (kt + 1 < NCH) {
            prefetchB(kt + 1); CPCOMMIT(); CPWAIT0();
            __syncthreads();
        }
    }

    if ((l & 3) == 0) {
        s_rowmin2[rA][wc] = rowMinA;
        s_rowmin2[rB][wc] = rowMinB;
    }
    __syncthreads();

    // ---- refilter by FINAL threshold, then exact sequential-FMA recheck ----
    {
        const int row = tid & 63;
        const int sl  = tid >> 6;
        const int cntr = s_cnt[row];
        const float zsq = g_zsq[m0 + row];
        const float w2  = 4.0f * 0.00390625f * sqrtf(zsq) * emax + 1.0e-3f;
        const float thr = fminf(s_rowmin2[row][0], s_rowmin2[row][1]) + w2;
        const float* zr = z + (size_t)(m0 + row) * DDIM;
        float bv = 3.4e38f;
        int   bi = 0x7fffffff;
        if (cntr <= SLOTS) {
            for (int s = sl; s < cntr; s += 4) {
                if (s_candv[row][s] > thr) continue;   // final-window refilter
                int k = s_candk[row][s];
                const float* cr = cb + (size_t)k * DDIM;
                float acc = 0.f;
                for (int d = 0; d < DDIM; d++)
                    acc = fmaf(__ldg(zr + d), __ldg(cr + d), acc);
                float v = __fadd_rn(fmaf(-2.f, acc, zsq), __ldg(&g_esq[k]));
                if (v < bv || (v == bv && k < bi)) { bv = v; bi = k; }
            }
        } else {   // overflow fallback (P ~ 0 with SLOTS=32): parallel full scan
            for (int k = sl; k < KC; k += 4) {
                const float* cr = cb + (size_t)k * DDIM;
                float acc = 0.f;
                for (int d = 0; d < DDIM; d++)
                    acc = fmaf(__ldg(zr + d), __ldg(cr + d), acc);
                float v = __fadd_rn(fmaf(-2.f, acc, zsq), __ldg(&g_esq[k]));
                if (v < bv || (v == bv && k < bi)) { bv = v; bi = k; }
            }
        }
        s_rv[row][sl] = bv;
        s_ri[row][sl] = bi;
    }
    __syncthreads();
    if (tid < BM) {
        float bv = s_rv[tid][0];
        int   bi = s_ri[tid][0];
        #pragma unroll
        for (int s = 1; s < 4; s++) {
            float v = s_rv[tid][s];
            int   k = s_ri[tid][s];
            if (v < bv || (v == bv && k < bi)) { bv = v; bi = k; }
        }
        bidx[tid] = bi;
    }
    __syncthreads();

    // ---- gather + write: out[0:ND] = fl(z + fl(zq - z)) (STE), out[ND:] = zq
    const float4* cb4 = reinterpret_cast<const float4*>(cb);
    const float4* z4  = reinterpret_cast<const float4*>(z);
    float4* out4 = reinterpret_cast<float4*>(out);
    const long long base = (long long)m0 * (DDIM / 4);
    for (int e = tid; e < BM * (DDIM / 4); e += 256) {
        int r = e >> 6;
        int c = e & 63;
        int k = bidx[r];
        float4 q  = cb4[k * (DDIM / 4) + c];
        float4 ze = z4[base + (long long)r * (DDIM / 4) + c];
        float4 st;
        st.x = __fadd_rn(ze.x, __fsub_rn(q.x, ze.x));
        st.y = __fadd_rn(ze.y, __fsub_rn(q.y, ze.y));
        st.z = __fadd_rn(ze.z, __fsub_rn(q.z, ze.z));
        st.w = __fadd_rn(ze.w, __fsub_rn(q.w, ze.w));
        out4[base + (long long)r * (DDIM / 4) + c] = st;
        if (qoff4 > 0)
            out4[qoff4 + base + (long long)r * (DDIM / 4) + c] = q;
    }
}

extern "C" void kernel_launch(void* const* d_in, const int* in_sizes, int n_in,
                              void* d_out, int out_size) {
    const float* z  = (const float*)d_in[0];
    const float* cb = (const float*)d_in[1];
    int Nrows = in_sizes[0] / DDIM;
    long long ND = (long long)Nrows * DDIM;
    long long qoff4 = ((long long)out_size >= 2 * ND) ? (ND / 4) : 0;

    cudaFuncSetAttribute(vq_main, cudaFuncAttributeMaxDynamicSharedMemorySize,
                         DYN_SMEM);

    int nbz = Nrows / 128;
    prep<<<CVT_BLKS + nbz + KC / 128, 128>>>(z, cb, nbz);
    vq_main<<<Nrows / BM, 256, DYN_SMEM>>>(z, cb, (float*)d_out, qoff4);
}

// round 16
// speedup vs baseline: 4.9722x; 1.1801x over previous
#include <cuda_runtime.h>
#include <cstdint>

#define DDIM 256
#define KC   512
#define BM   64
#define KN   64
#define NCH  (KC / KN)          // 8 code chunks
#define NMAX 131072
#define SLOTS 32
#define RSTRIDE 528             // 33x16B row stride: conflict-free ldmatrix (proven)
#define TILE_B  (BM * RSTRIDE)  // 33792
#define DYN_SMEM (2 * TILE_B)   // A + single B buffer = 67584

__device__ float g_esq[KC];
__device__ float g_zsq[NMAX];
__device__ int   g_emax_bits;                 // max_k ||e_k|| as float bits
__device__ uint32_t g_cbb[KC * DDIM / 2];     // bf16x2 codebook (256 KB)

__device__ __forceinline__ uint32_t sm_u32(const void* p) {
    uint32_t a;
    asm("{ .reg .u64 t; cvta.to.shared.u64 t, %1; cvt.u32.u64 %0, t; }"
        : "=r"(a) : "l"(p));
    return a;
}
#define STS128(a, r0, r1, r2, r3) \
    asm volatile("st.shared.v4.b32 [%0], {%1, %2, %3, %4};" \
                 :: "r"(a), "r"(r0), "r"(r1), "r"(r2), "r"(r3) : "memory")
#define LDMX4(r0, r1, r2, r3, addr) \
    asm volatile("ldmatrix.sync.aligned.m8n8.x4.shared.b16 {%0,%1,%2,%3}, [%4];" \
                 : "=r"(r0), "=r"(r1), "=r"(r2), "=r"(r3) : "r"(addr))
#define MMA16816(c, a0, a1, a2, a3, b0, b1) \
    asm volatile("mma.sync.aligned.m16n8k16.row.col.f32.bf16.bf16.f32 " \
                 "{%0,%1,%2,%3}, {%4,%5,%6,%7}, {%8,%9}, {%0,%1,%2,%3};" \
                 : "+f"((c)[0]), "+f"((c)[1]), "+f"((c)[2]), "+f"((c)[3]) \
                 : "r"(a0), "r"(a1), "r"(a2), "r"(a3), "r"(b0), "r"(b1))
#define CPASYNC16(dst, src) \
    asm volatile("cp.async.cg.shared.global [%0], [%1], 16;" \
                 :: "r"(dst), "l"(src) : "memory")
#define CPCOMMIT() asm volatile("cp.async.commit_group;" ::: "memory")
#define CPWAIT0()  asm volatile("cp.async.wait_group 0;" ::: "memory")

// ---- fused prologue: codebook bf16 convert + bitwise row sums (R3-proven) --
#define CVT_BLKS 512
__global__ __launch_bounds__(128)
void prep(const float* __restrict__ z, const float* __restrict__ cb, int nbz) {
    const int b = blockIdx.x;
    const int t = threadIdx.x;
    if (b < CVT_BLKS) {                         // bf16x2 codebook convert
        int i = b * 128 + t;                    // 65536 pairs
        float2 f = reinterpret_cast<const float2*>(cb)[i];
        uint32_t p;
        asm("cvt.rn.bf16x2.f32 %0, %1, %2;" : "=r"(p) : "f"(f.y), "f"(f.x));
        g_cbb[i] = p;
        return;
    }
    __shared__ float tile[128][33];
    const int rb = b - CVT_BLKS;
    const bool is_cb = (rb >= nbz);
    const float* src = is_cb ? cb : z;
    const int r0 = (is_cb ? (rb - nbz) : rb) * 128;
    float acc = 0.f;
    for (int d0 = 0; d0 < DDIM; d0 += 32) {
        __syncthreads();
        for (int e = t; e < 128 * 32; e += 128) {
            int r = e >> 5, c = e & 31;
            tile[r][c] = src[(size_t)(r0 + r) * DDIM + d0 + c];
        }
        __syncthreads();
        #pragma unroll
        for (int c = 0; c < 32; c++) {
            float v = tile[t][c];
            acc = __fadd_rn(acc, __fmul_rn(v, v));   // strict sequential order
        }
    }
    if (is_cb) {
        g_esq[r0 + t] = acc;
        atomicMax(&g_emax_bits, __float_as_int(sqrtf(acc)));
    } else {
        g_zsq[r0 + t] = acc;
    }
}

// ------ main kernel: R14 body + reg cap (2 CTA/SM) + esq staged in smem -----
__global__ __launch_bounds__(256, 2)
void vq_main(const float* __restrict__ z, const float* __restrict__ cb,
             float* __restrict__ out, long long qoff4) {
    extern __shared__ __align__(16) char dsm[];
    __shared__ float s_esq[KC];             // staged once: kills per-chunk LDGs
    __shared__ int   s_cnt[BM];
    __shared__ int   s_candk[BM][SLOTS];
    __shared__ float s_candv[BM][SLOTS];
    __shared__ float s_rowmin2[BM][2];      // per code-half running min
    __shared__ int   s_ri[BM][4];
    __shared__ float s_rv[BM][4];
    __shared__ int   bidx[BM];

    const int tid = threadIdx.x;
    const int w   = tid >> 5;
    const int l   = tid & 31;
    const int m0  = blockIdx.x * BM;
    const uint32_t Ab = sm_u32(dsm);
    const uint32_t Bb = Ab + TILE_B;

    if (tid < BM) s_cnt[tid] = 0;
    s_esq[tid]       = g_esq[tid];
    s_esq[tid + 256] = g_esq[tid + 256];

    auto prefetchB = [&](int kt) {
        const char* src = reinterpret_cast<const char*>(g_cbb)
                        + (size_t)kt * KN * DDIM * 2;
        #pragma unroll
        for (int it = 0; it < 8; it++) {
            int u = tid + it * 256;            // 0..2047: 64 rows x 32 x 16B
            int r = u >> 5, c = u & 31;
            CPASYNC16(Bb + (uint32_t)(r * RSTRIDE + c * 16),
                      src + (size_t)r * 512 + c * 16);
        }
    };

    prefetchB(0); CPCOMMIT();
    {   // load A tile: fp32 -> bf16 rn -> padded smem rows
        const float* src = z + (size_t)m0 * DDIM;
        #pragma unroll
        for (int it = 0; it < 8; it++) {
            int u = tid + it * 256;
            int r = u >> 5, c = u & 31;
            const float* p = src + (size_t)r * DDIM + c * 8;
            float4 f0 = __ldg(reinterpret_cast<const float4*>(p));
            float4 f1 = __ldg(reinterpret_cast<const float4*>(p + 4));
            uint32_t p0, p1, p2, p3;
            asm("cvt.rn.bf16x2.f32 %0, %1, %2;" : "=r"(p0) : "f"(f0.y), "f"(f0.x));
            asm("cvt.rn.bf16x2.f32 %0, %1, %2;" : "=r"(p1) : "f"(f0.w), "f"(f0.z));
            asm("cvt.rn.bf16x2.f32 %0, %1, %2;" : "=r"(p2) : "f"(f1.y), "f"(f1.x));
            asm("cvt.rn.bf16x2.f32 %0, %1, %2;" : "=r"(p3) : "f"(f1.w), "f"(f1.z));
            STS128(Ab + (uint32_t)(r * RSTRIDE + c * 16), p0, p1, p2, p3);
        }
    }
    CPWAIT0();
    __syncthreads();

    const int wr = w & 3;              // row group: rows wr*16 .. +16
    const int wc = w >> 2;             // code half of each chunk
    const int mid = l >> 3, rr = l & 7;
    const int rA = wr * 16 + (l >> 2);
    const int rB = rA + 8;
    const float zsqA = g_zsq[m0 + rA];
    const float zsqB = g_zsq[m0 + rB];
    const float emax = __int_as_float(g_emax_bits);
    const float W2A = 4.0f * 0.00390625f * sqrtf(zsqA) * emax + 1.0e-3f;
    const float W2B = 4.0f * 0.00390625f * sqrtf(zsqB) * emax + 1.0e-3f;
    float rowMinA = 3.4e38f, rowMinB = 3.4e38f;

    for (int kt = 0; kt < NCH; kt++) {
        float acc[4][4];
        #pragma unroll
        for (int nt = 0; nt < 4; nt++)
            #pragma unroll
            for (int c = 0; c < 4; c++) acc[nt][c] = 0.f;

        #pragma unroll
        for (int ks = 0; ks < 16; ks++) {
            uint32_t a0, a1, a2, a3;
            LDMX4(a0, a1, a2, a3,
                  Ab + (uint32_t)((wr * 16 + (mid & 1) * 8 + rr) * RSTRIDE
                       + (ks * 2 + (mid >> 1)) * 16));
            #pragma unroll
            for (int ntp = 0; ntp < 2; ntp++) {
                uint32_t b0, b1, b2, b3;
                LDMX4(b0, b1, b2, b3,
                      Bb + (uint32_t)((wc * 32 + ntp * 16 + (mid >> 1) * 8 + rr)
                           * RSTRIDE + (ks * 2 + (mid & 1)) * 16));
                MMA16816(acc[2 * ntp],     a0, a1, a2, a3, b0, b1);
                MMA16816(acc[2 * ntp + 1], a0, a1, a2, a3, b2, b3);
            }
        }

        // pass 1: running per-row min (this warp's code half)
        float tminA = 3.4e38f, tminB = 3.4e38f;
        #pragma unroll
        for (int nt = 0; nt < 4; nt++) {
            #pragma unroll
            for (int c = 0; c < 2; c++) {
                int col = kt * KN + wc * 32 + nt * 8 + 2 * (l & 3) + c;
                float esq = s_esq[col];
                float va = __fadd_rn(fmaf(-2.f, acc[nt][c],     zsqA), esq);
                float vb = __fadd_rn(fmaf(-2.f, acc[nt][2 + c], zsqB), esq);
                tminA = fminf(tminA, va);
                tminB = fminf(tminB, vb);
            }
        }
        tminA = fminf(tminA, __shfl_xor_sync(0xffffffffu, tminA, 1));
        tminA = fminf(tminA, __shfl_xor_sync(0xffffffffu, tminA, 2));
        tminB = fminf(tminB, __shfl_xor_sync(0xffffffffu, tminB, 1));
        tminB = fminf(tminB, __shfl_xor_sync(0xffffffffu, tminB, 2));
        rowMinA = fminf(rowMinA, tminA);
        rowMinB = fminf(rowMinB, tminB);
        const float thrA = rowMinA + W2A;   // running thr >= final thr:
        const float thrB = rowMinB + W2B;   // containment preserved

        // pass 2: collect (k, v) candidates within the running window
        #pragma unroll
        for (int nt = 0; nt < 4; nt++) {
            #pragma unroll
            for (int c = 0; c < 2; c++) {
                int col = kt * KN + wc * 32 + nt * 8 + 2 * (l & 3) + c;
                float esq = s_esq[col];
                float va = __fadd_rn(fmaf(-2.f, acc[nt][c],     zsqA), esq);
                float vb = __fadd_rn(fmaf(-2.f, acc[nt][2 + c], zsqB), esq);
                if (va <= thrA) {
                    int s = atomicAdd(&s_cnt[rA], 1);
                    if (s < SLOTS) { s_candk[rA][s] = col; s_candv[rA][s] = va; }
                }
                if (vb <= thrB) {
                    int s = atomicAdd(&s_cnt[rB], 1);
                    if (s < SLOTS) { s_candk[rB][s] = col; s_candv[rB][s] = vb; }
                }
            }
        }

        __syncthreads();                     // all warps done reading B tile
        if (kt + 1 < NCH) {
            prefetchB(kt + 1); CPCOMMIT(); CPWAIT0();
            __syncthreads();
        }
    }

    if ((l & 3) == 0) {
        s_rowmin2[rA][wc] = rowMinA;
        s_rowmin2[rB][wc] = rowMinB;
    }
    __syncthreads();

    // ---- refilter by FINAL threshold, then exact sequential-FMA recheck ----
    {
        const int row = tid & 63;
        const int sl  = tid >> 6;
        const int cntr = s_cnt[row];
        const float zsq = g_zsq[m0 + row];
        const float w2  = 4.0f * 0.00390625f * sqrtf(zsq) * emax + 1.0e-3f;
        const float thr = fminf(s_rowmin2[row][0], s_rowmin2[row][1]) + w2;
        const float* zr = z + (size_t)(m0 + row) * DDIM;
        float bv = 3.4e38f;
        int   bi = 0x7fffffff;
        if (cntr <= SLOTS) {
            for (int s = sl; s < cntr; s += 4) {
                if (s_candv[row][s] > thr) continue;   // final-window refilter
                int k = s_candk[row][s];
                const float* cr = cb + (size_t)k * DDIM;
                float acc = 0.f;
                for (int d = 0; d < DDIM; d++)
                    acc = fmaf(__ldg(zr + d), __ldg(cr + d), acc);
                float v = __fadd_rn(fmaf(-2.f, acc, zsq), s_esq[k]);
                if (v < bv || (v == bv && k < bi)) { bv = v; bi = k; }
            }
        } else {   // overflow fallback (P ~ 0 with SLOTS=32): parallel full scan
            for (int k = sl; k < KC; k += 4) {
                const float* cr = cb + (size_t)k * DDIM;
                float acc = 0.f;
                for (int d = 0; d < DDIM; d++)
                    acc = fmaf(__ldg(zr + d), __ldg(cr + d), acc);
                float v = __fadd_rn(fmaf(-2.f, acc, zsq), s_esq[k]);
                if (v < bv || (v == bv && k < bi)) { bv = v; bi = k; }
            }
        }
        s_rv[row][sl] = bv;
        s_ri[row][sl] = bi;
    }
    __syncthreads();
    if (tid < BM) {
        float bv = s_rv[tid][0];
        int   bi = s_ri[tid][0];
        #pragma unroll
        for (int s = 1; s < 4; s++) {
            float v = s_rv[tid][s];
            int   k = s_ri[tid][s];
            if (v < bv || (v == bv && k < bi)) { bv = v; bi = k; }
        }
        bidx[tid] = bi;
    }
    __syncthreads();

    // ---- gather + write: out[0:ND] = fl(z + fl(zq - z)) (STE), out[ND:] = zq
    const float4* cb4 = reinterpret_cast<const float4*>(cb);
    const float4* z4  = reinterpret_cast<const float4*>(z);
    float4* out4 = reinterpret_cast<float4*>(out);
    const long long base = (long long)m0 * (DDIM / 4);
    for (int e = tid; e < BM * (DDIM / 4); e += 256) {
        int r = e >> 6;
        int c = e & 63;
        int k = bidx[r];
        float4 q  = cb4[k * (DDIM / 4) + c];
        float4 ze = z4[base + (long long)r * (DDIM / 4) + c];
        float4 st;
        st.x = __fadd_rn(ze.x, __fsub_rn(q.x, ze.x));
        st.y = __fadd_rn(ze.y, __fsub_rn(q.y, ze.y));
        st.z = __fadd_rn(ze.z, __fsub_rn(q.z, ze.z));
        st.w = __fadd_rn(ze.w, __fsub_rn(q.w, ze.w));
        out4[base + (long long)r * (DDIM / 4) + c] = st;
        if (qoff4 > 0)
            out4[qoff4 + base + (long long)r * (DDIM / 4) + c] = q;
    }
}

extern "C" void kernel_launch(void* const* d_in, const int* in_sizes, int n_in,
                              void* d_out, int out_size) {
    const float* z  = (const float*)d_in[0];
    const float* cb = (const float*)d_in[1];
    int Nrows = in_sizes[0] / DDIM;
    long long ND = (long long)Nrows * DDIM;
    long long qoff4 = ((long long)out_size >= 2 * ND) ? (ND / 4) : 0;

    cudaFuncSetAttribute(vq_main, cudaFuncAttributeMaxDynamicSharedMemorySize,
                         DYN_SMEM);

    int nbz = Nrows / 128;
    prep<<<CVT_BLKS + nbz + KC / 128, 128>>>(z, cb, nbz);
    vq_main<<<Nrows / BM, 256, DYN_SMEM>>>(z, cb, (float*)d_out, qoff4);
}